// round 1
// baseline (speedup 1.0000x reference)
#include <cuda_runtime.h>
#include <math.h>

#define NPTS 200000
#define KC   512
#define DIM  128
#define TN   64          // emb rows per block
#define TKC  64          // center cols per chunk
#define NCHUNK (KC/TKC)  // 8
#define DS   32          // d-slice for B staging
#define NSLICE (DIM/DS)  // 4

// Scratch (no allocations allowed)
__device__ float               g_c2[KC];
__device__ unsigned long long  g_pack[KC];
__device__ float               g_rowmin[NPTS];
__device__ double              g_loss;

// Per-launch init: reset argmin packs, precompute ||c||^2
__global__ void init_kernel(const float* __restrict__ cents) {
    int k = blockIdx.x * blockDim.x + threadIdx.x;
    if (k < KC) {
        g_pack[k] = 0xFFFFFFFFFFFFFFFFULL;
        const float* c = cents + (size_t)k * DIM;
        float s = 0.f;
#pragma unroll 16
        for (int d = 0; d < DIM; d++) s += c[d] * c[d];
        g_c2[k] = s;
    }
}

__global__ __launch_bounds__(256) void dist_kernel(const float* __restrict__ embs,
                                                   const float* __restrict__ cents) {
    __shared__ float sA[DIM][TN];         // 32 KB, transposed emb tile
    __shared__ float sB[DS][TKC];         //  8 KB, transposed center slice
    __shared__ float sX2[TN];
    __shared__ float sC2[TKC];
    __shared__ float sRedV[16][TN];       //  4 KB
    __shared__ unsigned char sRedI[16][TN];

    const int tid = threadIdx.x;
    const int tx = tid & 15;              // col group
    const int ty = tid >> 4;              // row group
    const int base = blockIdx.x * TN;

    // ---- Load A tile transposed: lanes vary r (consecutive) -> STS conflict-free ----
#pragma unroll
    for (int it = 0; it < 8; it++) {
        int f  = tid + it * 256;          // 0..2047
        int r  = f & 63;
        int dq = f >> 6;                  // 0..31
        float4 v = *reinterpret_cast<const float4*>(embs + (size_t)(base + r) * DIM + dq * 4);
        sA[dq*4+0][r] = v.x;
        sA[dq*4+1][r] = v.y;
        sA[dq*4+2][r] = v.z;
        sA[dq*4+3][r] = v.w;
    }
    __syncthreads();

    // ---- ||x||^2 per row (threads 0..63; lane r -> bank r, conflict-free) ----
    if (tid < TN) {
        float s = 0.f;
#pragma unroll 16
        for (int d = 0; d < DIM; d++) { float a = sA[d][tid]; s += a * a; }
        sX2[tid] = s;
    }

    float rmin[4] = {3.4e38f, 3.4e38f, 3.4e38f, 3.4e38f};  // min over cols of (c2 - 2*dot)

    for (int kc = 0; kc < NCHUNK; kc++) {
        __syncthreads();                   // prev epilogue readers done (and sX2 visible on kc=0)
        if (tid < TKC) sC2[tid] = g_c2[kc * TKC + tid];

        float acc[4][4];
#pragma unroll
        for (int i = 0; i < 4; i++)
#pragma unroll
            for (int j = 0; j < 4; j++) acc[i][j] = 0.f;

        for (int ds = 0; ds < NSLICE; ds++) {
            if (ds) __syncthreads();       // prev slice's compute done reading sB
            // load center slice transposed (conflict-free STS as above)
#pragma unroll
            for (int it = 0; it < 2; it++) {
                int f  = tid + it * 256;   // 0..511
                int c  = f & 63;
                int dq = f >> 6;           // 0..7
                float4 v = *reinterpret_cast<const float4*>(
                    cents + (size_t)(kc * TKC + c) * DIM + ds * DS + dq * 4);
                sB[dq*4+0][c] = v.x;
                sB[dq*4+1][c] = v.y;
                sB[dq*4+2][c] = v.z;
                sB[dq*4+3][c] = v.w;
            }
            __syncthreads();

#pragma unroll
            for (int dd = 0; dd < DS; dd++) {
                int d = ds * DS + dd;
                float4 a = *reinterpret_cast<const float4*>(&sA[d][ty * 4]);
                float4 b = *reinterpret_cast<const float4*>(&sB[dd][tx * 4]);
                float av[4] = {a.x, a.y, a.z, a.w};
                float bv[4] = {b.x, b.y, b.z, b.w};
#pragma unroll
                for (int i = 0; i < 4; i++)
#pragma unroll
                    for (int j = 0; j < 4; j++)
                        acc[i][j] += av[i] * bv[j];
            }
        }

        // ---- chunk epilogue ----
#pragma unroll
        for (int j = 0; j < 4; j++) {
            float c2 = sC2[tx * 4 + j];
            float bestv = 3.4e38f; int besti = 0;
#pragma unroll
            for (int i = 0; i < 4; i++) {
                float m2 = -2.f * acc[i][j];
                rmin[i] = fminf(rmin[i], c2 + m2);           // row-min (x2 added at end)
                float tv = sX2[ty * 4 + i] + m2;             // col-argmin (c2 added later)
                if (tv < bestv) { bestv = tv; besti = i; }   // strict < keeps lowest row
            }
            sRedV[ty][tx * 4 + j] = bestv;
            sRedI[ty][tx * 4 + j] = (unsigned char)(ty * 4 + besti);
        }
        __syncthreads();
        if (tid < TKC) {
            int col = tid;
            float bv = sRedV[0][col]; int br = sRedI[0][col];
#pragma unroll
            for (int u = 1; u < 16; u++) {
                float v = sRedV[u][col];
                int   r = sRedI[u][col];
                if (v < bv || (v == bv && r < br)) { bv = v; br = r; }
            }
            float d2 = fmaxf(bv + sC2[col], 0.f);
            unsigned long long pk =
                ((unsigned long long)__float_as_uint(d2) << 32) | (unsigned)(base + br);
            atomicMin(&g_pack[kc * TKC + col], pk);
        }
        // sRedV reuse protected by loop-head __syncthreads
    }

    // ---- row-min finalize ----
    __syncthreads();
#pragma unroll
    for (int i = 0; i < 4; i++) sRedV[tx][ty * 4 + i] = rmin[i];
    __syncthreads();
    if (tid < TN) {
        float m = sRedV[0][tid];
#pragma unroll
        for (int u = 1; u < 16; u++) m = fminf(m, sRedV[u][tid]);
        float d2 = fmaxf(sX2[tid] + m, 1e-12f);
        g_rowmin[base + tid] = sqrtf(d2);
    }
}

// Deterministic fixed-order sum (fp64 accumulation, fixed tree)
__global__ void loss_kernel() {
    __shared__ double sd[256];
    int t = threadIdx.x;
    double s = 0.0;
    for (int i = t; i < NPTS; i += 256) s += (double)g_rowmin[i];
    sd[t] = s;
    __syncthreads();
    for (int o = 128; o > 0; o >>= 1) {
        if (t < o) sd[t] += sd[t + o];
        __syncthreads();
    }
    if (t == 0) g_loss = sd[0];
}

// Output layout (float32): [centers (K*D)] [rep_ids (K)] [loss (1)]
__global__ void out_kernel(const float* __restrict__ cents, float* __restrict__ out, int out_size) {
    int i = blockIdx.x * blockDim.x + threadIdx.x;
    if (i >= out_size) return;
    if (i < KC * DIM) {
        out[i] = cents[i];
    } else if (i < KC * DIM + KC) {
        out[i] = (float)(unsigned)(g_pack[i - KC * DIM] & 0xFFFFFFFFu);
    } else {
        out[i] = (float)g_loss;
    }
}

extern "C" void kernel_launch(void* const* d_in, const int* in_sizes, int n_in,
                              void* d_out, int out_size) {
    const float* embs  = (const float*)d_in[0];
    const float* cents = (const float*)d_in[1];
    if (n_in >= 2 && in_sizes[0] == KC * DIM && in_sizes[1] == NPTS * DIM) {
        // defensive: inputs arrived in (centers, embs) order
        const float* t = embs; embs = cents; cents = t;
    }

    init_kernel<<<1, KC>>>(cents);
    dist_kernel<<<NPTS / TN, 256>>>(embs, cents);
    loss_kernel<<<1, 256>>>();
    out_kernel<<<(out_size + 255) / 256, 256>>>(cents, (float*)d_out, out_size);
}

// round 14
// speedup vs baseline: 3.2082x; 3.2082x over previous
#include <cuda_runtime.h>
#include <cuda_fp16.h>
#include <math.h>

#define NPTS 200000
#define KC   512
#define DIM  128
#define TM   128
#define KH   256
#define NTILES ((NPTS + TM - 1) / TM)   // 1563
#define GRID 152
#define CPH  (GRID/2)                   // 76

// ---- dynamic smem layout (bytes) ----
#define S_BHI 0          // B hi fp16  256 rows x 256B (64 KB), XOR-swizzled 16B chunks
#define S_BLO 65536
#define S_AHI 131072     // A hi fp16  128 rows x 256B (32 KB)
#define S_ALO 163840
#define S_C2  196608     // c2[256] f32
#define S_X2  197632     // x2[128] f32
#define S_CV  198144     // cand val [256][4]
#define S_CR  202240     // cand row [256][4]
#define S_RM  206336     // rowmin [128][2]
#define S_BV  207360     // running best val [256]
#define S_BR  208384     // running best row [256]
#define SMEM_TOTAL 209408

__device__ unsigned int       g_rowmin[NPTS];
__device__ unsigned long long g_pack[KC];
__device__ float              g_c2[KC];
__device__ double             g_partial[256];
__device__ double             g_loss;

// ---------------- helpers ----------------
__device__ __forceinline__ unsigned smem_u32(const void* p) {
    unsigned a;
    asm("{ .reg .u64 t; cvta.to.shared.u64 t, %1; cvt.u32.u64 %0, t; }" : "=r"(a) : "l"(p));
    return a;
}
__device__ __forceinline__ void ldsm_x4(unsigned addr, unsigned& r0, unsigned& r1,
                                        unsigned& r2, unsigned& r3) {
    asm volatile("ldmatrix.sync.aligned.m8n8.x4.shared.b16 {%0,%1,%2,%3}, [%4];"
                 : "=r"(r0), "=r"(r1), "=r"(r2), "=r"(r3) : "r"(addr));
}
__device__ __forceinline__ void mma16816(float* c, const unsigned* a, unsigned b0, unsigned b1) {
    asm volatile("mma.sync.aligned.m16n8k16.row.col.f32.f16.f16.f32 "
                 "{%0,%1,%2,%3}, {%4,%5,%6,%7}, {%8,%9}, {%0,%1,%2,%3};"
                 : "+f"(c[0]), "+f"(c[1]), "+f"(c[2]), "+f"(c[3])
                 : "r"(a[0]), "r"(a[1]), "r"(a[2]), "r"(a[3]), "r"(b0), "r"(b1));
}
#define STS64(addr, a, b) \
    asm volatile("st.shared.v2.b32 [%0], {%1,%2};" :: "r"(addr), "r"(a), "r"(b) : "memory")

// convert 4 fp32 -> hi/lo fp16 pairs, accumulate x2
__device__ __forceinline__ void cvt4(float4 v, unsigned& h01, unsigned& h23,
                                     unsigned& l01, unsigned& l23, float& x2) {
    float f[4] = {v.x, v.y, v.z, v.w};
    unsigned hh[4], hl[4];
#pragma unroll
    for (int i = 0; i < 4; i++) {
        __half a = __float2half_rn(f[i]);
        __half b = __float2half_rn(f[i] - __half2float(a));
        hh[i] = (unsigned)__half_as_ushort(a);
        hl[i] = (unsigned)__half_as_ushort(b);
        x2 += f[i] * f[i];
    }
    h01 = hh[0] | (hh[1] << 16); h23 = hh[2] | (hh[3] << 16);
    l01 = hl[0] | (hl[1] << 16); l23 = hl[2] | (hl[3] << 16);
}

// ---------------- kernels ----------------
__global__ void init_kernel(const float* __restrict__ cents) {
    int i = blockIdx.x * blockDim.x + threadIdx.x;
    if (i < NPTS) g_rowmin[i] = 0x7F800000u;
    if (i < KC) {
        g_pack[i] = 0xFFFFFFFFFFFFFFFFULL;
        const float* c = cents + (size_t)i * DIM;
        float s = 0.f;
#pragma unroll 16
        for (int d = 0; d < DIM; d++) s += c[d] * c[d];
        g_c2[i] = s;
    }
}

__global__ void __launch_bounds__(256, 1) dist_kernel(const float* __restrict__ embs,
                                                      const float* __restrict__ cents) {
    extern __shared__ char smem[];
    const unsigned sbase = smem_u32(smem);
    const int tid = threadIdx.x, lane = tid & 31, wid = tid >> 5;
    const int ch  = blockIdx.x & 1;
    const int cta = blockIdx.x >> 1;

    float*    sC2 = (float*)(smem + S_C2);
    float*    sX2 = (float*)(smem + S_X2);
    float*    sCV = (float*)(smem + S_CV);
    unsigned* sCR = (unsigned*)(smem + S_CR);
    float*    sRM = (float*)(smem + S_RM);
    float*    sBV = (float*)(smem + S_BV);
    unsigned* sBR = (unsigned*)(smem + S_BR);

    sBV[tid] = 1e30f;
    sBR[tid] = 0u;
    sC2[tid] = g_c2[ch * KH + tid];

    // ---- stage B half once: 256 rows x 32 float4 each -> hi/lo fp16 swizzled ----
#pragma unroll
    for (int it = 0; it < 32; it++) {
        int f = it * 256 + tid;              // 0..8191
        int row = f >> 5, q = f & 31;        // q = float4 index within row (0..31)
        float4 v = ((const float4*)cents)[(size_t)(ch * KH + row) * 32 + q];
        unsigned h01, h23, l01, l23; float d = 0.f;
        cvt4(v, h01, h23, l01, l23, d);
        unsigned off = row * 256 + (((q >> 1) ^ (row & 7)) << 4) + (q & 1) * 8;
        STS64(sbase + S_BHI + off, h01, h23);
        STS64(sbase + S_BLO + off, l01, l23);
    }
    __syncthreads();

    const int wr = wid & 3, wc = wid >> 2;
    const int g  = lane >> 2, t = lane & 3;
    const int la = lane & 7, lb = (lane >> 3) & 1, lc = lane >> 4;

    // A ldmatrix per-lane row bases
    unsigned aHiB[2], aLoB[2];
#pragma unroll
    for (int mt = 0; mt < 2; mt++) {
        int rowA = wr * 32 + mt * 16 + la + lb * 8;
        aHiB[mt] = sbase + S_AHI + rowA * 256;
        aLoB[mt] = sbase + S_ALO + rowA * 256;
    }

    for (int ti = cta; ti < NTILES; ti += CPH) {
        const int base = ti * TM;

        // ---- stage A tile: 128 rows x 32 float4; one warp covers one row per iter ----
#pragma unroll
        for (int it = 0; it < 16; it++) {
            int f = it * 256 + tid;          // 0..4095
            int row = f >> 5, q = f & 31;
            int grow = base + row;
            float4 v = make_float4(0.f, 0.f, 0.f, 0.f);
            if (grow < NPTS) v = ((const float4*)embs)[(size_t)grow * 32 + q];
            unsigned h01, h23, l01, l23; float x2 = 0.f;
            cvt4(v, h01, h23, l01, l23, x2);
            unsigned off = row * 256 + (((q >> 1) ^ (row & 7)) << 4) + (q & 1) * 8;
            STS64(sbase + S_AHI + off, h01, h23);
            STS64(sbase + S_ALO + off, l01, l23);
            x2 += __shfl_xor_sync(0xffffffffu, x2, 1);
            x2 += __shfl_xor_sync(0xffffffffu, x2, 2);
            x2 += __shfl_xor_sync(0xffffffffu, x2, 4);
            x2 += __shfl_xor_sync(0xffffffffu, x2, 8);
            x2 += __shfl_xor_sync(0xffffffffu, x2, 16);
            if (lane == 0) sX2[row] = (grow < NPTS) ? x2 : 5e29f;
        }
        __syncthreads();

        float rmin[4] = {1e30f, 1e30f, 1e30f, 1e30f};

        for (int cn = 0; cn < 2; cn++) {
            const int colbase = wc * 128 + cn * 64;
            unsigned bHiB[4], bLoB[4];
#pragma unroll
            for (int p = 0; p < 4; p++) {
                int rowB = colbase + p * 16 + la + lc * 8;
                bHiB[p] = sbase + S_BHI + rowB * 256;
                bLoB[p] = sbase + S_BLO + rowB * 256;
            }

            float acc[2][8][4];
#pragma unroll
            for (int mt = 0; mt < 2; mt++)
#pragma unroll
                for (int nt = 0; nt < 8; nt++)
#pragma unroll
                    for (int r = 0; r < 4; r++) acc[mt][nt][r] = 0.f;

#pragma unroll
            for (int kc = 0; kc < 8; kc++) {
                unsigned offA = (unsigned)(((kc * 2 + lc) ^ la) << 4);
                unsigned offB = (unsigned)(((kc * 2 + lb) ^ la) << 4);
                unsigned ah[2][4], av[2][4], bh[4][4], bl[4][4];
#pragma unroll
                for (int mt = 0; mt < 2; mt++) {
                    ldsm_x4(aHiB[mt] + offA, ah[mt][0], ah[mt][1], ah[mt][2], ah[mt][3]);
                    ldsm_x4(aLoB[mt] + offA, av[mt][0], av[mt][1], av[mt][2], av[mt][3]);
                }
#pragma unroll
                for (int p = 0; p < 4; p++) {
                    ldsm_x4(bHiB[p] + offB, bh[p][0], bh[p][1], bh[p][2], bh[p][3]);
                    ldsm_x4(bLoB[p] + offB, bl[p][0], bl[p][1], bl[p][2], bl[p][3]);
                }
#pragma unroll
                for (int mt = 0; mt < 2; mt++)
#pragma unroll
                    for (int p = 0; p < 4; p++) {
                        mma16816(acc[mt][2*p],     ah[mt], bh[p][0], bh[p][1]);
                        mma16816(acc[mt][2*p],     ah[mt], bl[p][0], bl[p][1]);
                        mma16816(acc[mt][2*p],     av[mt], bh[p][0], bh[p][1]);
                        mma16816(acc[mt][2*p + 1], ah[mt], bh[p][2], bh[p][3]);
                        mma16816(acc[mt][2*p + 1], ah[mt], bl[p][2], bl[p][3]);
                        mma16816(acc[mt][2*p + 1], av[mt], bh[p][2], bh[p][3]);
                    }
            }

            // ---- pass epilogue: row-mins + per-column argmin ----
            float x2r[4];
#pragma unroll
            for (int i = 0; i < 4; i++)
                x2r[i] = sX2[wr * 32 + (i >> 1) * 16 + (i & 1) * 8 + g];

#pragma unroll
            for (int nt = 0; nt < 8; nt++) {
                float c2a = sC2[colbase + nt * 8 + t * 2];
                float c2b = sC2[colbase + nt * 8 + t * 2 + 1];
#pragma unroll
                for (int j = 0; j < 2; j++) {
                    float c2 = j ? c2b : c2a;
                    float bv = 1e30f; unsigned br = 0u;
#pragma unroll
                    for (int i = 0; i < 4; i++) {
                        float nd = -2.f * acc[i >> 1][nt][(i & 1) * 2 + j];
                        rmin[i] = fminf(rmin[i], c2 + nd);
                        float v = x2r[i] + nd;
                        if (v < bv) {  // rows ascend with i -> earliest kept
                            bv = v;
                            br = (unsigned)(base + wr * 32 + (i >> 1) * 16 + (i & 1) * 8 + g);
                        }
                    }
#pragma unroll
                    for (int o = 4; o <= 16; o <<= 1) {
                        float ov = __shfl_xor_sync(0xffffffffu, bv, o);
                        unsigned orr = __shfl_xor_sync(0xffffffffu, br, o);
                        if (ov < bv || (ov == bv && orr < br)) { bv = ov; br = orr; }
                    }
                    if (g == 0) {
                        int col = colbase + nt * 8 + t * 2 + j;
                        sCV[col * 4 + wr] = bv;
                        sCR[col * 4 + wr] = br;
                    }
                }
            }
        }

        // row-min across t lanes, publish
#pragma unroll
        for (int i = 0; i < 4; i++) {
            float m = rmin[i];
            m = fminf(m, __shfl_xor_sync(0xffffffffu, m, 1));
            m = fminf(m, __shfl_xor_sync(0xffffffffu, m, 2));
            if (t == 0)
                sRM[(wr * 32 + (i >> 1) * 16 + (i & 1) * 8 + g) * 2 + wc] = m;
        }
        __syncthreads();

        // combine per-column candidates (thread = column)
        {
            float bv = sCV[tid * 4]; unsigned br = sCR[tid * 4];
#pragma unroll
            for (int s = 1; s < 4; s++) {
                float v = sCV[tid * 4 + s];
                unsigned r = sCR[tid * 4 + s];
                if (v < bv || (v == bv && r < br)) { bv = v; br = r; }
            }
            if (bv < sBV[tid]) { sBV[tid] = bv; sBR[tid] = br; }
            else if (bv == sBV[tid] && br < sBR[tid]) sBR[tid] = br;
        }
        // row-mins -> global
        if (tid < TM) {
            int grow = base + tid;
            if (grow < NPTS) {
                float m = fminf(sRM[tid * 2], sRM[tid * 2 + 1]);
                float d2 = fmaxf(sX2[tid] + m, 0.f);
                atomicMin(&g_rowmin[grow], __float_as_uint(d2));
            }
        }
        __syncthreads();
    }

    // flush per-CTA argmins (one atomic per center)
    {
        float bv = sBV[tid];
        if (bv < 1e30f) {
            float d2 = fmaxf(bv + sC2[tid], 0.f);
            unsigned long long pk =
                ((unsigned long long)__float_as_uint(d2) << 32) | sBR[tid];
            atomicMin(&g_pack[ch * KH + tid], pk);
        }
    }
}

__global__ void loss1_kernel() {
    __shared__ double sd[256];
    int b = blockIdx.x, t = threadIdx.x;
    double s = 0.0;
    for (int i = t; i < 1000; i += 256) {
        float d2 = __uint_as_float(g_rowmin[b * 1000 + i]);
        s += (double)sqrtf(fmaxf(d2, 1e-12f));
    }
    sd[t] = s;
    __syncthreads();
    for (int o = 128; o > 0; o >>= 1) { if (t < o) sd[t] += sd[t + o]; __syncthreads(); }
    if (t == 0) g_partial[b] = sd[0];
}

__global__ void loss2_kernel() {
    __shared__ double sd[256];
    int t = threadIdx.x;
    sd[t] = (t < 200) ? g_partial[t] : 0.0;
    __syncthreads();
    for (int o = 128; o > 0; o >>= 1) { if (t < o) sd[t] += sd[t + o]; __syncthreads(); }
    if (t == 0) g_loss = sd[0];
}

// Output: [centers (K*D)] [rep_ids (K)] [loss (1)]
__global__ void out_kernel(const float* __restrict__ cents, float* __restrict__ out, int out_size) {
    int i = blockIdx.x * blockDim.x + threadIdx.x;
    if (i >= out_size) return;
    if (i < KC * DIM) out[i] = cents[i];
    else if (i < KC * DIM + KC) out[i] = (float)(unsigned)(g_pack[i - KC * DIM] & 0xFFFFFFFFu);
    else out[i] = (float)g_loss;
}

extern "C" void kernel_launch(void* const* d_in, const int* in_sizes, int n_in,
                              void* d_out, int out_size) {
    const float* embs  = (const float*)d_in[0];
    const float* cents = (const float*)d_in[1];
    if (n_in >= 2 && in_sizes[0] == KC * DIM && in_sizes[1] == NPTS * DIM) {
        const float* t = embs; embs = cents; cents = t;
    }
    cudaFuncSetAttribute(dist_kernel, cudaFuncAttributeMaxDynamicSharedMemorySize, SMEM_TOTAL);

    init_kernel<<<(NPTS + 255) / 256, 256>>>(cents);
    dist_kernel<<<GRID, 256, SMEM_TOTAL>>>(embs, cents);
    loss1_kernel<<<200, 256>>>();
    loss2_kernel<<<1, 256>>>();
    out_kernel<<<(out_size + 255) / 256, 256>>>(cents, (float*)d_out, out_size);
}